// round 3
// baseline (speedup 1.0000x reference)
#include <cuda_runtime.h>

#define THREADS 256
#define Q 6
#define DIM 1024
#define ROWS_PER_CHUNK 16   // 8 warps x 2 rows

__global__ __launch_bounds__(THREADS)
void ffq_kernel(const float* __restrict__ x,
                const float* __restrict__ w1,
                const float* __restrict__ b1,
                const float* __restrict__ theta,
                const float* __restrict__ w2,
                const float* __restrict__ b2,
                float* __restrict__ out,
                int n_rows)
{
    __shared__ float w1s[Q][DIM];                 // 24 KB
    __shared__ float qvs[ROWS_PER_CHUNK][8];      // q-values per chunk row (padded)

    const int tid  = threadIdx.x;
    const int wid  = tid >> 5;
    const int lane = tid & 31;

    // ---- Stage w1 into SMEM: 6144 floats = 1536 float4, 6 per thread ----
    {
        const float4* __restrict__ w1v  = (const float4*)w1;
        float4* w1sv = (float4*)&w1s[0][0];
        #pragma unroll
        for (int i = 0; i < 6; i++)
            w1sv[tid + i * THREADS] = w1v[tid + i * THREADS];
    }

    // ---- Per-thread constants ----
    float b1r[Q], ctr[Q];
    #pragma unroll
    for (int q = 0; q < Q; q++) {
        b1r[q] = __ldg(&b1[q]);
        ctr[q] = cosf(__ldg(&theta[q]));
    }

    // ---- Register-stationary w2 slice: thread t owns d = 4t..4t+3 ----
    const int d0 = tid * 4;
    float w2r[4][Q], b2r[4];
    #pragma unroll
    for (int j = 0; j < 4; j++) {
        b2r[j] = __ldg(&b2[d0 + j]);
        #pragma unroll
        for (int q = 0; q < Q; q++)
            w2r[j][q] = __ldg(&w2[(d0 + j) * Q + q]);
    }
    __syncthreads();

    const int n_chunks = n_rows / ROWS_PER_CHUNK;
    for (int c = blockIdx.x; c < n_chunks; c += gridDim.x) {
        const int base = c * ROWS_PER_CHUNK;

        // ================= Phase A: proj + quantum expvals =================
        // Warp `wid` handles rows base+2*wid and base+2*wid+1.
        {
            const int rA = base + wid * 2;
            const int rB = rA + 1;
            const float4* __restrict__ xA = (const float4*)(x + (size_t)rA * DIM);
            const float4* __restrict__ xB = (const float4*)(x + (size_t)rB * DIM);

            float sA[Q], sB[Q];
            #pragma unroll
            for (int q = 0; q < Q; q++) { sA[q] = 0.f; sB[q] = 0.f; }

            #pragma unroll
            for (int i = 0; i < 8; i++) {
                const int col = i * 32 + lane;        // float4 index: coalesced
                const float4 a = __ldcs(&xA[col]);
                const float4 b = __ldcs(&xB[col]);
                #pragma unroll
                for (int q = 0; q < Q; q++) {
                    const float4 w = *(const float4*)&w1s[q][col * 4];
                    sA[q] += a.x * w.x + a.y * w.y + a.z * w.z + a.w * w.w;
                    sB[q] += b.x * w.x + b.y * w.y + b.z * w.z + b.w * w.w;
                }
            }

            // Butterfly reduce 6 partial sums per row across the warp.
            #pragma unroll
            for (int off = 16; off > 0; off >>= 1) {
                #pragma unroll
                for (int q = 0; q < Q; q++) {
                    sA[q] += __shfl_xor_sync(0xffffffffu, sA[q], off);
                    sB[q] += __shfl_xor_sync(0xffffffffu, sB[q], off);
                }
            }

            if (lane == 0) {
                #pragma unroll
                for (int q = 0; q < Q; q++) {
                    qvs[wid * 2 + 0][q] = __cosf(sA[q] + b1r[q]) * ctr[q];
                    qvs[wid * 2 + 1][q] = __cosf(sB[q] + b1r[q]) * ctr[q];
                }
            }
        }
        __syncthreads();

        // ================= Phase B: out = relu(q @ w2^T + b2) =================
        #pragma unroll 4
        for (int r = 0; r < ROWS_PER_CHUNK; r++) {
            float a0 = b2r[0], a1 = b2r[1], a2 = b2r[2], a3 = b2r[3];
            #pragma unroll
            for (int q = 0; q < Q; q++) {
                const float qv = qvs[r][q];           // SMEM broadcast
                a0 += qv * w2r[0][q];
                a1 += qv * w2r[1][q];
                a2 += qv * w2r[2][q];
                a3 += qv * w2r[3][q];
            }
            float4 o;
            o.x = fmaxf(a0, 0.f);
            o.y = fmaxf(a1, 0.f);
            o.z = fmaxf(a2, 0.f);
            o.w = fmaxf(a3, 0.f);
            *(float4*)(out + (size_t)(base + r) * DIM + d0) = o;
        }
        __syncthreads();   // protect qvs before next chunk's phase A
    }
}

extern "C" void kernel_launch(void* const* d_in, const int* in_sizes, int n_in,
                              void* d_out, int out_size)
{
    const float* x     = (const float*)d_in[0];
    const float* w1    = (const float*)d_in[1];
    const float* b1    = (const float*)d_in[2];
    const float* theta = (const float*)d_in[3];
    const float* w2    = (const float*)d_in[4];
    const float* b2    = (const float*)d_in[5];
    float* out = (float*)d_out;

    const int n_rows = in_sizes[0] / DIM;   // 65536

    const int grid = 1184;                   // 148 SMs * 8, grid-stride over chunks
    ffq_kernel<<<grid, THREADS>>>(x, w1, b1, theta, w2, b2, out, n_rows);
}

// round 4
// speedup vs baseline: 1.1221x; 1.1221x over previous
#include <cuda_runtime.h>

#define THREADS 256
#define Q 6
#define DIM 1024
#define ROWS_PER_CHUNK 16   // 8 warps x 2 rows
#define GRID 296            // 148 SMs * 2 resident blocks: one persistent wave

__global__ __launch_bounds__(THREADS, 2)
void ffq_kernel(const float* __restrict__ x,
                const float* __restrict__ w1,
                const float* __restrict__ b1,
                const float* __restrict__ theta,
                const float* __restrict__ w2,
                const float* __restrict__ b2,
                float* __restrict__ out,
                int n_rows)
{
    __shared__ float w1s[Q][DIM];                 // 24 KB
    __shared__ float qvs[ROWS_PER_CHUNK][8];      // q-values per chunk row (padded)
    __shared__ float qc[2][8];                    // [0]=b1, [1]=cos(theta) (lane-0 use only)

    const int tid  = threadIdx.x;
    const int wid  = tid >> 5;
    const int lane = tid & 31;

    // ---- Stage w1 into SMEM: 6144 floats = 1536 float4, 6 per thread ----
    {
        const float4* __restrict__ w1v  = (const float4*)w1;
        float4* w1sv = (float4*)&w1s[0][0];
        #pragma unroll
        for (int i = 0; i < 6; i++)
            w1sv[tid + i * THREADS] = w1v[tid + i * THREADS];
    }
    if (tid < Q) {
        qc[0][tid] = b1[tid];
        qc[1][tid] = cosf(theta[tid]);
    }

    // ---- Register-stationary w2 slice: thread t owns d = 4t..4t+3 ----
    const int d0 = tid * 4;
    float w2r[4][Q], b2r[4];
    #pragma unroll
    for (int j = 0; j < 4; j++) {
        b2r[j] = __ldg(&b2[d0 + j]);
        #pragma unroll
        for (int q = 0; q < Q; q++)
            w2r[j][q] = __ldg(&w2[(d0 + j) * Q + q]);
    }
    __syncthreads();

    const int n_chunks = n_rows / ROWS_PER_CHUNK;
    const int step = gridDim.x;
    int c = blockIdx.x;
    if (c >= n_chunks) return;

    const float4* __restrict__ xv = (const float4*)x;

    // ---- Prologue: prefetch chunk c's two rows for this warp into registers ----
    float4 bufA[8], bufB[8];
    {
        const size_t rA = (size_t)(c * ROWS_PER_CHUNK + wid * 2) * (DIM / 4);
        #pragma unroll
        for (int i = 0; i < 8; i++) {
            bufA[i] = __ldcs(&xv[rA +       i * 32 + lane]);
            bufB[i] = __ldcs(&xv[rA + 256 + i * 32 + lane]);
        }
    }

    for (; c < n_chunks; c += step) {
        // Next chunk to prefetch (clamped to current when past the end: valid,
        // deterministic, results unused).
        int cn = c + step;
        if (cn >= n_chunks) cn = c;
        const size_t rAn = (size_t)(cn * ROWS_PER_CHUNK + wid * 2) * (DIM / 4);

        // ================= Phase A: consume buffer, re-issue loads =================
        float sA[Q], sB[Q];
        #pragma unroll
        for (int q = 0; q < Q; q++) { sA[q] = 0.f; sB[q] = 0.f; }

        #pragma unroll
        for (int i = 0; i < 8; i++) {
            const float4 a = bufA[i];
            const float4 b = bufB[i];
            // Issue next-chunk loads NOW: they stay in flight through the
            // reduce, both barriers, and phase B of this chunk.
            bufA[i] = __ldcs(&xv[rAn +       i * 32 + lane]);
            bufB[i] = __ldcs(&xv[rAn + 256 + i * 32 + lane]);

            const int col4 = (i * 32 + lane) * 4;
            #pragma unroll
            for (int q = 0; q < Q; q++) {
                const float4 w = *(const float4*)&w1s[q][col4];
                sA[q] = fmaf(a.w, w.w, fmaf(a.z, w.z, fmaf(a.y, w.y, fmaf(a.x, w.x, sA[q]))));
                sB[q] = fmaf(b.w, w.w, fmaf(b.z, w.z, fmaf(b.y, w.y, fmaf(b.x, w.x, sB[q]))));
            }
        }

        // Butterfly reduce 6 partial sums per row across the warp.
        #pragma unroll
        for (int off = 16; off > 0; off >>= 1) {
            #pragma unroll
            for (int q = 0; q < Q; q++) {
                sA[q] += __shfl_xor_sync(0xffffffffu, sA[q], off);
                sB[q] += __shfl_xor_sync(0xffffffffu, sB[q], off);
            }
        }

        if (lane == 0) {
            #pragma unroll
            for (int q = 0; q < Q; q++) {
                qvs[wid * 2 + 0][q] = __cosf(sA[q] + qc[0][q]) * qc[1][q];
                qvs[wid * 2 + 1][q] = __cosf(sB[q] + qc[0][q]) * qc[1][q];
            }
        }
        __syncthreads();

        // ================= Phase B: out = relu(q @ w2^T + b2) =================
        const size_t ob = (size_t)c * ROWS_PER_CHUNK * DIM + d0;
        #pragma unroll 4
        for (int r = 0; r < ROWS_PER_CHUNK; r++) {
            float a0 = b2r[0], a1 = b2r[1], a2 = b2r[2], a3 = b2r[3];
            #pragma unroll
            for (int q = 0; q < Q; q++) {
                const float qv = qvs[r][q];           // SMEM broadcast
                a0 = fmaf(qv, w2r[0][q], a0);
                a1 = fmaf(qv, w2r[1][q], a1);
                a2 = fmaf(qv, w2r[2][q], a2);
                a3 = fmaf(qv, w2r[3][q], a3);
            }
            float4 o;
            o.x = fmaxf(a0, 0.f);
            o.y = fmaxf(a1, 0.f);
            o.z = fmaxf(a2, 0.f);
            o.w = fmaxf(a3, 0.f);
            __stcs((float4*)(out + ob + (size_t)r * DIM), o);
        }
        __syncthreads();   // protect qvs before next chunk's phase A
    }
}

extern "C" void kernel_launch(void* const* d_in, const int* in_sizes, int n_in,
                              void* d_out, int out_size)
{
    const float* x     = (const float*)d_in[0];
    const float* w1    = (const float*)d_in[1];
    const float* b1    = (const float*)d_in[2];
    const float* theta = (const float*)d_in[3];
    const float* w2    = (const float*)d_in[4];
    const float* b2    = (const float*)d_in[5];
    float* out = (float*)d_out;

    const int n_rows = in_sizes[0] / DIM;   // 65536

    ffq_kernel<<<GRID, THREADS>>>(x, w1, b1, theta, w2, b2, out, n_rows);
}

// round 5
// speedup vs baseline: 1.1246x; 1.0022x over previous
#include <cuda_runtime.h>

#define THREADS 256
#define Q 6
#define DIM 1024
#define ROWS_PER_CHUNK 16   // 8 warps x 2 rows
#define GRID 296            // 148 SMs * 2 resident blocks: one persistent wave

__global__ __launch_bounds__(THREADS, 2)
void ffq_kernel(const float* __restrict__ x,
                const float* __restrict__ w1,
                const float* __restrict__ b1,
                const float* __restrict__ theta,
                const float* __restrict__ w2,
                const float* __restrict__ b2,
                float* __restrict__ out,
                int n_rows)
{
    __shared__ float w1s[Q][DIM];                 // 24 KB
    __shared__ float qvs[ROWS_PER_CHUNK][8];      // q-values per chunk row (padded)
    __shared__ float qc[2][8];                    // [0]=b1, [1]=cos(theta) (lane-0 use only)

    const int tid  = threadIdx.x;
    const int wid  = tid >> 5;
    const int lane = tid & 31;

    // ---- Stage w1 into SMEM: 6144 floats = 1536 float4, 6 per thread ----
    {
        const float4* __restrict__ w1v  = (const float4*)w1;
        float4* w1sv = (float4*)&w1s[0][0];
        #pragma unroll
        for (int i = 0; i < 6; i++)
            w1sv[tid + i * THREADS] = w1v[tid + i * THREADS];
    }
    if (tid < Q) {
        qc[0][tid] = b1[tid];
        qc[1][tid] = cosf(theta[tid]);
    }

    // ---- Register-stationary w2 slice: thread t owns d = 4t..4t+3 ----
    const int d0 = tid * 4;
    float w2r[4][Q], b2r[4];
    #pragma unroll
    for (int j = 0; j < 4; j++) {
        b2r[j] = __ldg(&b2[d0 + j]);
        #pragma unroll
        for (int q = 0; q < Q; q++)
            w2r[j][q] = __ldg(&w2[(d0 + j) * Q + q]);
    }
    __syncthreads();

    const int n_chunks = n_rows / ROWS_PER_CHUNK;
    const int step = gridDim.x;
    int c = blockIdx.x;
    if (c >= n_chunks) return;

    const float4* __restrict__ xv = (const float4*)x;

    // ---- Prologue: prefetch chunk c's two rows for this warp into registers ----
    float4 bufA[8], bufB[8];
    {
        const size_t rA = (size_t)(c * ROWS_PER_CHUNK + wid * 2) * (DIM / 4);
        #pragma unroll
        for (int i = 0; i < 8; i++) {
            bufA[i] = __ldcs(&xv[rA +       i * 32 + lane]);
            bufB[i] = __ldcs(&xv[rA + 256 + i * 32 + lane]);
        }
    }

    for (; c < n_chunks; c += step) {
        // Next chunk to prefetch (clamped to current when past the end: valid,
        // deterministic, results unused).
        int cn = c + step;
        if (cn >= n_chunks) cn = c;
        const size_t rAn = (size_t)(cn * ROWS_PER_CHUNK + wid * 2) * (DIM / 4);

        // ================= Phase A: consume buffer, re-issue loads =================
        float sA[Q], sB[Q];
        #pragma unroll
        for (int q = 0; q < Q; q++) { sA[q] = 0.f; sB[q] = 0.f; }

        #pragma unroll
        for (int i = 0; i < 8; i++) {
            const float4 a = bufA[i];
            const float4 b = bufB[i];
            // Issue next-chunk loads NOW: they stay in flight through the
            // reduce, both barriers, and phase B of this chunk.
            bufA[i] = __ldcs(&xv[rAn +       i * 32 + lane]);
            bufB[i] = __ldcs(&xv[rAn + 256 + i * 32 + lane]);

            const int col4 = (i * 32 + lane) * 4;
            #pragma unroll
            for (int q = 0; q < Q; q++) {
                const float4 w = *(const float4*)&w1s[q][col4];
                sA[q] = fmaf(a.w, w.w, fmaf(a.z, w.z, fmaf(a.y, w.y, fmaf(a.x, w.x, sA[q]))));
                sB[q] = fmaf(b.w, w.w, fmaf(b.z, w.z, fmaf(b.y, w.y, fmaf(b.x, w.x, sB[q]))));
            }
        }

        // Butterfly reduce 6 partial sums per row across the warp.
        #pragma unroll
        for (int off = 16; off > 0; off >>= 1) {
            #pragma unroll
            for (int q = 0; q < Q; q++) {
                sA[q] += __shfl_xor_sync(0xffffffffu, sA[q], off);
                sB[q] += __shfl_xor_sync(0xffffffffu, sB[q], off);
            }
        }

        if (lane == 0) {
            #pragma unroll
            for (int q = 0; q < Q; q++) {
                qvs[wid * 2 + 0][q] = __cosf(sA[q] + qc[0][q]) * qc[1][q];
                qvs[wid * 2 + 1][q] = __cosf(sB[q] + qc[0][q]) * qc[1][q];
            }
        }
        __syncthreads();

        // ================= Phase B: out = relu(q @ w2^T + b2) =================
        const size_t ob = (size_t)c * ROWS_PER_CHUNK * DIM + d0;
        #pragma unroll 4
        for (int r = 0; r < ROWS_PER_CHUNK; r++) {
            float a0 = b2r[0], a1 = b2r[1], a2 = b2r[2], a3 = b2r[3];
            #pragma unroll
            for (int q = 0; q < Q; q++) {
                const float qv = qvs[r][q];           // SMEM broadcast
                a0 = fmaf(qv, w2r[0][q], a0);
                a1 = fmaf(qv, w2r[1][q], a1);
                a2 = fmaf(qv, w2r[2][q], a2);
                a3 = fmaf(qv, w2r[3][q], a3);
            }
            float4 o;
            o.x = fmaxf(a0, 0.f);
            o.y = fmaxf(a1, 0.f);
            o.z = fmaxf(a2, 0.f);
            o.w = fmaxf(a3, 0.f);
            __stcs((float4*)(out + ob + (size_t)r * DIM), o);
        }
        __syncthreads();   // protect qvs before next chunk's phase A
    }
}

extern "C" void kernel_launch(void* const* d_in, const int* in_sizes, int n_in,
                              void* d_out, int out_size)
{
    const float* x     = (const float*)d_in[0];
    const float* w1    = (const float*)d_in[1];
    const float* b1    = (const float*)d_in[2];
    const float* theta = (const float*)d_in[3];
    const float* w2    = (const float*)d_in[4];
    const float* b2    = (const float*)d_in[5];
    float* out = (float*)d_out;

    const int n_rows = in_sizes[0] / DIM;   // 65536

    ffq_kernel<<<GRID, THREADS>>>(x, w1, b1, theta, w2, b2, out, n_rows);
}

// round 6
// speedup vs baseline: 1.1341x; 1.0084x over previous
#include <cuda_runtime.h>

#define THREADS 256
#define Q 6
#define DIM 1024
#define ROWS_PER_CHUNK 16   // 8 warps x 2 rows
#define GRID 296            // 148 SMs * 2 resident blocks: one persistent wave

__global__ __launch_bounds__(THREADS, 2)
void ffq_kernel(const float* __restrict__ x,
                const float* __restrict__ w1,
                const float* __restrict__ b1,
                const float* __restrict__ theta,
                const float* __restrict__ w2,
                const float* __restrict__ b2,
                float* __restrict__ out,
                int n_rows)
{
    __shared__ float w1s[Q][DIM];                 // 24 KB
    __shared__ float qvs[ROWS_PER_CHUNK][8];      // q-values per chunk row (padded)
    __shared__ float qc[2][8];                    // [0]=b1, [1]=cos(theta) (lane-0 use only)

    const int tid  = threadIdx.x;
    const int wid  = tid >> 5;
    const int lane = tid & 31;

    // ---- Stage w1 into SMEM: 6144 floats = 1536 float4, 6 per thread ----
    {
        const float4* __restrict__ w1v  = (const float4*)w1;
        float4* w1sv = (float4*)&w1s[0][0];
        #pragma unroll
        for (int i = 0; i < 6; i++)
            w1sv[tid + i * THREADS] = w1v[tid + i * THREADS];
    }
    if (tid < Q) {
        qc[0][tid] = b1[tid];
        qc[1][tid] = cosf(theta[tid]);
    }

    // ---- Register-stationary w2 slice: thread t owns d = 4t..4t+3 ----
    const int d0 = tid * 4;
    float w2r[4][Q], b2r[4];
    #pragma unroll
    for (int j = 0; j < 4; j++) {
        b2r[j] = __ldg(&b2[d0 + j]);
        #pragma unroll
        for (int q = 0; q < Q; q++)
            w2r[j][q] = __ldg(&w2[(d0 + j) * Q + q]);
    }
    __syncthreads();

    const int n_chunks = n_rows / ROWS_PER_CHUNK;
    const int step = gridDim.x;
    int c = blockIdx.x;
    if (c >= n_chunks) return;

    const float4* __restrict__ xv = (const float4*)x;

    // ---- Prologue: prefetch chunk c's two rows for this warp into registers ----
    float4 bufA[8], bufB[8];
    {
        const size_t rA = (size_t)(c * ROWS_PER_CHUNK + wid * 2) * (DIM / 4);
        #pragma unroll
        for (int i = 0; i < 8; i++) {
            bufA[i] = __ldcs(&xv[rA +       i * 32 + lane]);
            bufB[i] = __ldcs(&xv[rA + 256 + i * 32 + lane]);
        }
    }

    for (; c < n_chunks; c += step) {
        // Next chunk to prefetch (clamped to current when past the end: valid,
        // deterministic, results unused).
        int cn = c + step;
        if (cn >= n_chunks) cn = c;
        const size_t rAn = (size_t)(cn * ROWS_PER_CHUNK + wid * 2) * (DIM / 4);

        // ================= Phase A: consume buffer, re-issue loads =================
        float sA[Q], sB[Q];
        #pragma unroll
        for (int q = 0; q < Q; q++) { sA[q] = 0.f; sB[q] = 0.f; }

        #pragma unroll
        for (int i = 0; i < 8; i++) {
            const float4 a = bufA[i];
            const float4 b = bufB[i];
            // Issue next-chunk loads NOW: they stay in flight through the
            // reduce, both barriers, and phase B of this chunk.
            bufA[i] = __ldcs(&xv[rAn +       i * 32 + lane]);
            bufB[i] = __ldcs(&xv[rAn + 256 + i * 32 + lane]);

            const int col4 = (i * 32 + lane) * 4;
            #pragma unroll
            for (int q = 0; q < Q; q++) {
                const float4 w = *(const float4*)&w1s[q][col4];
                sA[q] = fmaf(a.w, w.w, fmaf(a.z, w.z, fmaf(a.y, w.y, fmaf(a.x, w.x, sA[q]))));
                sB[q] = fmaf(b.w, w.w, fmaf(b.z, w.z, fmaf(b.y, w.y, fmaf(b.x, w.x, sB[q]))));
            }
        }

        // Butterfly reduce 6 partial sums per row across the warp.
        #pragma unroll
        for (int off = 16; off > 0; off >>= 1) {
            #pragma unroll
            for (int q = 0; q < Q; q++) {
                sA[q] += __shfl_xor_sync(0xffffffffu, sA[q], off);
                sB[q] += __shfl_xor_sync(0xffffffffu, sB[q], off);
            }
        }

        if (lane == 0) {
            #pragma unroll
            for (int q = 0; q < Q; q++) {
                qvs[wid * 2 + 0][q] = __cosf(sA[q] + qc[0][q]) * qc[1][q];
                qvs[wid * 2 + 1][q] = __cosf(sB[q] + qc[0][q]) * qc[1][q];
            }
        }
        __syncthreads();

        // ================= Phase B: out = relu(q @ w2^T + b2) =================
        const size_t ob = (size_t)c * ROWS_PER_CHUNK * DIM + d0;
        #pragma unroll 4
        for (int r = 0; r < ROWS_PER_CHUNK; r++) {
            float a0 = b2r[0], a1 = b2r[1], a2 = b2r[2], a3 = b2r[3];
            #pragma unroll
            for (int q = 0; q < Q; q++) {
                const float qv = qvs[r][q];           // SMEM broadcast
                a0 = fmaf(qv, w2r[0][q], a0);
                a1 = fmaf(qv, w2r[1][q], a1);
                a2 = fmaf(qv, w2r[2][q], a2);
                a3 = fmaf(qv, w2r[3][q], a3);
            }
            float4 o;
            o.x = fmaxf(a0, 0.f);
            o.y = fmaxf(a1, 0.f);
            o.z = fmaxf(a2, 0.f);
            o.w = fmaxf(a3, 0.f);
            __stcs((float4*)(out + ob + (size_t)r * DIM), o);
        }
        __syncthreads();   // protect qvs before next chunk's phase A
    }
}

extern "C" void kernel_launch(void* const* d_in, const int* in_sizes, int n_in,
                              void* d_out, int out_size)
{
    const float* x     = (const float*)d_in[0];
    const float* w1    = (const float*)d_in[1];
    const float* b1    = (const float*)d_in[2];
    const float* theta = (const float*)d_in[3];
    const float* w2    = (const float*)d_in[4];
    const float* b2    = (const float*)d_in[5];
    float* out = (float*)d_out;

    const int n_rows = in_sizes[0] / DIM;   // 65536

    ffq_kernel<<<GRID, THREADS>>>(x, w1, b1, theta, w2, b2, out, n_rows);
}